// round 1
// baseline (speedup 1.0000x reference)
#include <cuda_runtime.h>

#define NN 8192          // nodes
#define NE 16384         // edges
#define RS 32            // row stripes in column-reduce pass
#define STRIPE (NN / RS) // 256 rows per stripe
#define K3_GRID 296      // 2 balanced waves of 148 SMs

// Scratch (device globals — no allocation allowed)
__device__ float g_u[NN];
__device__ float g_v[NN];
__device__ float g_c[NN];
__device__ float g_ai[NE];
__device__ float g_ao[NE];
__device__ float g_pai[RS][NE];
__device__ float g_pao[RS][NE];

// K1: per-node scalars u = X·k1, v = X·k2, c = X·k3
__global__ void k1_prep(const float* __restrict__ X, const float* __restrict__ kw) {
    int n = blockIdx.x * blockDim.x + threadIdx.x;
    if (n >= NN) return;
    float4 x = reinterpret_cast<const float4*>(X)[n];
    g_u[n] = x.x * kw[0] + x.y * kw[1] + x.z * kw[2]  + x.w * kw[3];
    g_v[n] = x.x * kw[4] + x.y * kw[5] + x.z * kw[6]  + x.w * kw[7];
    g_c[n] = x.x * kw[8] + x.y * kw[9] + x.z * kw[10] + x.w * kw[11];
}

// K2: column-reduce partials over a 256-row stripe.
//   pai[s][e] += Ro[n,e]*u[n]   (-> ai)
//   pao[s][e] += Ri[n,e]*v[n]   (-> ao)
// Block = 256 threads, each thread owns 4 consecutive columns (one float4).
// Grid = (NE/1024, RS) = (16, 32) = 512 blocks.
__global__ __launch_bounds__(256) void k2_colreduce(const float* __restrict__ Ri,
                                                    const float* __restrict__ Ro) {
    __shared__ float su[STRIPE];
    __shared__ float sv[STRIPE];
    int t = threadIdx.x;
    int col = blockIdx.x * 1024 + t * 4;
    int row0 = blockIdx.y * STRIPE;
    su[t] = g_u[row0 + t];
    sv[t] = g_v[row0 + t];
    __syncthreads();

    float4 ai = make_float4(0.f, 0.f, 0.f, 0.f);
    float4 ao = make_float4(0.f, 0.f, 0.f, 0.f);
    size_t base = (size_t)row0 * NE + col;
#pragma unroll 4
    for (int r = 0; r < STRIPE; ++r) {
        float4 a = *reinterpret_cast<const float4*>(Ri + base);
        float4 b = *reinterpret_cast<const float4*>(Ro + base);
        float vv = sv[r];
        float uu = su[r];
        ao.x += a.x * vv; ao.y += a.y * vv; ao.z += a.z * vv; ao.w += a.w * vv;
        ai.x += b.x * uu; ai.y += b.y * uu; ai.z += b.z * uu; ai.w += b.w * uu;
        base += NE;
    }
    *reinterpret_cast<float4*>(&g_pai[blockIdx.y][col]) = ai;
    *reinterpret_cast<float4*>(&g_pao[blockIdx.y][col]) = ao;
}

// K2b: reduce the RS partials and fold in edge weights e[e].
__global__ void k2b_finish(const float* __restrict__ ew) {
    int idx = blockIdx.x * blockDim.x + threadIdx.x;
    int col = idx * 4;
    if (col >= NE) return;
    float4 sai = make_float4(0.f, 0.f, 0.f, 0.f);
    float4 sao = make_float4(0.f, 0.f, 0.f, 0.f);
#pragma unroll
    for (int s = 0; s < RS; ++s) {
        float4 a = *reinterpret_cast<const float4*>(&g_pai[s][col]);
        float4 b = *reinterpret_cast<const float4*>(&g_pao[s][col]);
        sai.x += a.x; sai.y += a.y; sai.z += a.z; sai.w += a.w;
        sao.x += b.x; sao.y += b.y; sao.z += b.z; sao.w += b.w;
    }
    float4 w = *reinterpret_cast<const float4*>(ew + col);
    sai.x *= w.x; sai.y *= w.y; sai.z *= w.z; sai.w *= w.w;
    sao.x *= w.x; sao.y *= w.y; sao.z *= w.z; sao.w *= w.w;
    *reinterpret_cast<float4*>(&g_ai[col]) = sai;
    *reinterpret_cast<float4*>(&g_ao[col]) = sao;
}

// K3: row-reduce. out[n] = sum_e Ri[n,e]*ai[e] + Ro[n,e]*ao[e] + c[n].
// 1024 threads/block; each thread caches its 16 fixed columns of ai/ao in
// registers (8 float4), so ai/ao are read from L2 only once per block.
__global__ __launch_bounds__(1024) void k3_rowreduce(const float* __restrict__ Ri,
                                                     const float* __restrict__ Ro,
                                                     float* __restrict__ out) {
    __shared__ float sred[32];
    int t = threadIdx.x;
    float4 rai[4], rao[4];
#pragma unroll
    for (int g = 0; g < 4; ++g) {
        int col = g * 4096 + t * 4;
        rai[g] = *reinterpret_cast<const float4*>(&g_ai[col]);
        rao[g] = *reinterpret_cast<const float4*>(&g_ao[col]);
    }
    int r0 = (int)(((long long)blockIdx.x * NN) / gridDim.x);
    int r1 = (int)(((long long)(blockIdx.x + 1) * NN) / gridDim.x);
    for (int n = r0; n < r1; ++n) {
        const float* rowi = Ri + (size_t)n * NE;
        const float* rowo = Ro + (size_t)n * NE;
        float acc = 0.f;
#pragma unroll
        for (int g = 0; g < 4; ++g) {
            int col = g * 4096 + t * 4;
            float4 a = *reinterpret_cast<const float4*>(rowi + col);
            float4 b = *reinterpret_cast<const float4*>(rowo + col);
            acc += a.x * rai[g].x + a.y * rai[g].y + a.z * rai[g].z + a.w * rai[g].w
                 + b.x * rao[g].x + b.y * rao[g].y + b.z * rao[g].z + b.w * rao[g].w;
        }
#pragma unroll
        for (int off = 16; off; off >>= 1)
            acc += __shfl_down_sync(0xffffffffu, acc, off);
        if ((t & 31) == 0) sred[t >> 5] = acc;
        __syncthreads();
        if (t < 32) {
            float vsum = sred[t];
#pragma unroll
            for (int off = 16; off; off >>= 1)
                vsum += __shfl_down_sync(0xffffffffu, vsum, off);
            if (t == 0) out[n] = vsum + g_c[n];
        }
        __syncthreads();
    }
}

extern "C" void kernel_launch(void* const* d_in, const int* in_sizes, int n_in,
                              void* d_out, int out_size) {
    const float* X    = (const float*)d_in[0];  // [N,4]
    const float* ew   = (const float*)d_in[1];  // [E,1]
    const float* Ri   = (const float*)d_in[2];  // [N,E]
    const float* Ro   = (const float*)d_in[3];  // [N,E]
    const float* kern = (const float*)d_in[4];  // [12,1]
    float* out = (float*)d_out;                 // [N,1]

    k1_prep<<<NN / 256, 256>>>(X, kern);
    dim3 g2(NE / 1024, RS);
    k2_colreduce<<<g2, 256>>>(Ri, Ro);
    k2b_finish<<<(NE / 4 + 255) / 256, 256>>>(ew);
    k3_rowreduce<<<K3_GRID, 1024>>>(Ri, Ro, out);
}